// round 1
// baseline (speedup 1.0000x reference)
#include <cuda_runtime.h>
#include <cuda_bf16.h>
#include <math.h>

#define N_NODES 25000
#define N_EDGES 400000
#define HID 64
#define EMB 8
#define N_GRAPHS 16
#define N_CLASSES 10
#define KDIM 512   /* EMB*HID */

// ---------------- scratch (device globals; no allocation allowed) ----------
__device__ float g_B[(size_t)N_NODES * KDIM];     // 51.2 MB  B[n, i*64+j]
__device__ float g_hA[N_NODES * HID];
__device__ float g_hB[N_NODES * HID];
__device__ float g_R[N_NODES * HID];              // relu(agg)
__device__ float g_D[(size_t)N_EDGES * EMB];      // sorted edge directions
__device__ int   g_srcs[N_EDGES];                 // sorted srcs (CSR by dst)
__device__ int   g_rowptr[N_NODES + 1];
__device__ int   g_cnt[N_NODES];
__device__ int   g_cur[N_NODES];
__device__ float g_sums[HID];
__device__ float g_sumsq[HID];
__device__ float g_pooled[N_GRAPHS * HID];

// ---------------- CSR build ------------------------------------------------
__global__ void k_zero_cc() {
    int i = blockIdx.x * blockDim.x + threadIdx.x;
    if (i < N_NODES) { g_cnt[i] = 0; g_cur[i] = 0; }
}

__global__ void k_hist(const int* __restrict__ dst) {
    int e = blockIdx.x * blockDim.x + threadIdx.x;
    if (e < N_EDGES) atomicAdd(&g_cnt[dst[e]], 1);
}

// single-block exclusive scan over 25000 counts -> rowptr
__global__ void k_scan() {
    __shared__ int wsum[32];
    __shared__ int running;
    int tid = threadIdx.x, lane = tid & 31, wid = tid >> 5;
    if (tid == 0) running = 0;
    __syncthreads();
    for (int base = 0; base < N_NODES; base += 1024) {
        int i = base + tid;
        int v = (i < N_NODES) ? g_cnt[i] : 0;
        int x = v;
        #pragma unroll
        for (int o = 1; o < 32; o <<= 1) {
            int t = __shfl_up_sync(0xffffffffu, x, o);
            if (lane >= o) x += t;
        }
        if (lane == 31) wsum[wid] = x;
        __syncthreads();
        if (wid == 0) {
            int w = wsum[lane];
            #pragma unroll
            for (int o = 1; o < 32; o <<= 1) {
                int t = __shfl_up_sync(0xffffffffu, w, o);
                if (lane >= o) w += t;
            }
            wsum[lane] = w;
        }
        __syncthreads();
        int incl = x + (wid > 0 ? wsum[wid - 1] : 0);
        int r = running;
        if (i < N_NODES) g_rowptr[i] = r + incl - v;
        __syncthreads();
        if (tid == 1023) running += incl;   // incl of last thread == chunk total
        __syncthreads();
    }
    if (tid == 0) g_rowptr[N_NODES] = running;
}

// scatter edges to CSR slots; compute normalized direction d = (c[s]-c[t])/max(||.||,1e-12)
__global__ void k_scatter(const int* __restrict__ src, const int* __restrict__ dst,
                          const float* __restrict__ c) {
    int e = blockIdx.x * blockDim.x + threadIdx.x;
    if (e >= N_EDGES) return;
    int s = src[e], t = dst[e];
    float d[EMB];
    float nn = 0.f;
    #pragma unroll
    for (int i = 0; i < EMB; i++) {
        float v = c[s * EMB + i] - c[t * EMB + i];
        d[i] = v; nn += v * v;
    }
    float sc = 1.0f / fmaxf(sqrtf(nn), 1e-12f);
    int p = g_rowptr[t] + atomicAdd(&g_cur[t], 1);
    g_srcs[p] = s;
    #pragma unroll
    for (int i = 0; i < EMB; i++) g_D[(size_t)p * EMB + i] = d[i] * sc;
}

// ---------------- edge aggregation: B[n,i,j] = sum_{e:dst=n} d_i * h[src,j] ----
// one warp per dst node, 16 accumulator regs = full 8x64 tile
__global__ void k_edge_agg(const float* __restrict__ feat, int hsel) {
    if (blockIdx.x == 0) {   // piggyback: zero per-layer reduction buffers
        int t = threadIdx.x;
        if (t < HID) { g_sums[t] = 0.f; g_sumsq[t] = 0.f; }
        for (int i = t; i < N_GRAPHS * HID; i += blockDim.x) g_pooled[i] = 0.f;
    }
    const float* __restrict__ h = (hsel == 0) ? feat : ((hsel == 1) ? g_hA : g_hB);
    int w = (blockIdx.x * blockDim.x + threadIdx.x) >> 5;
    int lane = threadIdx.x & 31;
    if (w >= N_NODES) return;
    int e0 = g_rowptr[w], e1 = g_rowptr[w + 1];
    float a0[EMB], a1[EMB];
    #pragma unroll
    for (int i = 0; i < EMB; i++) { a0[i] = 0.f; a1[i] = 0.f; }
    for (int e = e0; e < e1; e++) {
        int s = g_srcs[e];
        float h0 = __ldg(&h[s * HID + lane]);
        float h1 = __ldg(&h[s * HID + 32 + lane]);
        const float* dp = &g_D[(size_t)e * EMB];
        #pragma unroll
        for (int i = 0; i < EMB; i++) {
            float di = __ldg(dp + i);
            a0[i] += di * h0;
            a1[i] += di * h1;
        }
    }
    float* out = &g_B[(size_t)w * KDIM];
    #pragma unroll
    for (int i = 0; i < EMB; i++) {
        out[i * HID + lane] = a0[i];
        out[i * HID + 32 + lane] = a1[i];
    }
}

// ---------------- SGEMM: R = relu(B[25000,512] @ W[512,64]) ----------------
#define BM 128
#define BK 32
__global__ void k_gemm_relu(const float* __restrict__ W) {
    __shared__ float As[BM][BK + 4];   // stride 36 floats (16B aligned, conflict-light)
    __shared__ float Bs[BK][HID];
    int tid = threadIdx.x;       // 256
    int tx = tid & 15;           // col group: cols tx*4 .. tx*4+3
    int ty = tid >> 4;           // row group: rows ty*8 .. ty*8+7
    int rowBase = blockIdx.x * BM;
    float acc[8][4];
    #pragma unroll
    for (int r = 0; r < 8; r++)
        #pragma unroll
        for (int cc = 0; cc < 4; cc++) acc[r][cc] = 0.f;

    for (int kb = 0; kb < KDIM; kb += BK) {
        // load A tile: 128 rows x 32 k = 1024 float4 (4 per thread)
        #pragma unroll
        for (int it = 0; it < 4; it++) {
            int f = tid + 256 * it;
            int r = f >> 3;          // 8 float4 per row
            int q = f & 7;
            int grow = rowBase + r;
            float4 v = make_float4(0.f, 0.f, 0.f, 0.f);
            if (grow < N_NODES)
                v = *(const float4*)&g_B[(size_t)grow * KDIM + kb + q * 4];
            *(float4*)&As[r][q * 4] = v;
        }
        // load W tile: 32 x 64 = 512 float4 (2 per thread)
        #pragma unroll
        for (int it = 0; it < 2; it++) {
            int f = tid + 256 * it;
            int k = f >> 4;
            int q = f & 15;
            *(float4*)&Bs[k][q * 4] = *(const float4*)&W[(kb + k) * HID + q * 4];
        }
        __syncthreads();
        #pragma unroll
        for (int kk = 0; kk < BK; kk++) {
            float4 b4 = *(float4*)&Bs[kk][tx * 4];
            float a[8];
            #pragma unroll
            for (int r = 0; r < 8; r++) a[r] = As[ty * 8 + r][kk];
            #pragma unroll
            for (int r = 0; r < 8; r++) {
                acc[r][0] += a[r] * b4.x;
                acc[r][1] += a[r] * b4.y;
                acc[r][2] += a[r] * b4.z;
                acc[r][3] += a[r] * b4.w;
            }
        }
        __syncthreads();
    }
    #pragma unroll
    for (int r = 0; r < 8; r++) {
        int grow = rowBase + ty * 8 + r;
        if (grow < N_NODES) {
            float4 v = make_float4(fmaxf(acc[r][0], 0.f), fmaxf(acc[r][1], 0.f),
                                   fmaxf(acc[r][2], 0.f), fmaxf(acc[r][3], 0.f));
            *(float4*)&g_R[grow * HID + tx * 4] = v;
        }
    }
}

// ---------------- BN stats: column sums / sumsq of R -----------------------
__global__ void k_bn_stats() {
    int tid = threadIdx.x;       // 256
    int k = tid & 63, nl = tid >> 6;
    float s = 0.f, s2 = 0.f;
    for (int n = blockIdx.x * 4 + nl; n < N_NODES; n += gridDim.x * 4) {
        float v = g_R[n * HID + k];
        s += v; s2 += v * v;
    }
    __shared__ float sm[256], sm2[256];
    sm[tid] = s; sm2[tid] = s2;
    __syncthreads();
    if (nl == 0) {
        float ts = sm[k] + sm[64 + k] + sm[128 + k] + sm[192 + k];
        float t2 = sm2[k] + sm2[64 + k] + sm2[128 + k] + sm2[192 + k];
        atomicAdd(&g_sums[k], ts);
        atomicAdd(&g_sumsq[k], t2);
    }
}

// ---------------- BN normalize + shortcut + per-graph pooling --------------
__global__ void k_norm_pool(const float* __restrict__ feat, int hinsel, int houtsel,
                            const float* __restrict__ gamma, const float* __restrict__ beta,
                            const int* __restrict__ gids, int shortcut) {
    const float* __restrict__ hin = (hinsel == 0) ? feat : ((hinsel == 1) ? g_hA : g_hB);
    float* hout = (houtsel == 1) ? g_hA : g_hB;
    int tid = threadIdx.x;        // 512 -> 8 nodes x 64 cols per block
    int k = tid & 63, nl = tid >> 6;
    int n = blockIdx.x * 8 + nl;  // 3125*8 == 25000 exactly

    __shared__ float ps[N_GRAPHS * HID];
    for (int i = tid; i < N_GRAPHS * HID; i += 512) ps[i] = 0.f;
    __syncthreads();

    const float inv = 1.0f / (float)N_NODES;
    float mu = g_sums[k] * inv;
    float var = g_sumsq[k] * inv - mu * mu;
    float rstd = rsqrtf(var + 1e-5f);
    float v = gamma[k] * (g_R[n * HID + k] - mu) * rstd + beta[k];
    if (shortcut) v += hin[n * HID + k];
    hout[n * HID + k] = v;

    int g = gids[n];
    atomicAdd(&ps[g * HID + k], v);
    __syncthreads();

    int gmin = gids[blockIdx.x * 8];
    int gmax = gids[blockIdx.x * 8 + 7];        // ids sorted -> contiguous span
    int span = (gmax - gmin + 1) * HID;
    for (int i = tid; i < span; i += 512)
        atomicAdd(&g_pooled[gmin * HID + i], ps[gmin * HID + i]);
}

// ---------------- classifier on pooled [16,64] -----------------------------
__global__ void k_classifier(const float* __restrict__ cW1, const float* __restrict__ cb1,
                             const float* __restrict__ cg1, const float* __restrict__ cbt1,
                             const float* __restrict__ cW2, const float* __restrict__ cb2,
                             float* __restrict__ out, int accumulate) {
    __shared__ float xp[N_GRAPHS * HID];   // 1024
    __shared__ float y[N_GRAPHS * 32];     // 512
    __shared__ float mu[32], rs[32];
    int tid = threadIdx.x;  // 512
    for (int i = tid; i < N_GRAPHS * HID; i += 512) xp[i] = g_pooled[i];
    __syncthreads();
    {
        int r = tid >> 5, c = tid & 31;
        float acc = cb1[c];
        #pragma unroll 8
        for (int j = 0; j < HID; j++) acc += xp[r * HID + j] * cW1[j * 32 + c];
        y[r * 32 + c] = acc;
    }
    __syncthreads();
    if (tid < 32) {
        float s = 0.f, s2 = 0.f;
        #pragma unroll
        for (int r = 0; r < N_GRAPHS; r++) {
            float v = y[r * 32 + tid];
            s += v; s2 += v * v;
        }
        float m = s / (float)N_GRAPHS;
        float var = s2 / (float)N_GRAPHS - m * m;
        mu[tid] = m;
        rs[tid] = rsqrtf(var + 1e-5f);
    }
    __syncthreads();
    {
        int r = tid >> 5, c = tid & 31;
        float v = cg1[c] * (y[r * 32 + c] - mu[c]) * rs[c] + cbt1[c];
        y[r * 32 + c] = fmaxf(v, 0.f);
    }
    __syncthreads();
    if (tid < N_GRAPHS * N_CLASSES) {
        int r = tid / N_CLASSES, c = tid % N_CLASSES;
        float acc = cb2[c];
        #pragma unroll
        for (int j = 0; j < 32; j++) acc += y[r * 32 + j] * cW2[j * N_CLASSES + c];
        if (accumulate) out[r * N_CLASSES + c] += acc;
        else            out[r * N_CLASSES + c] = acc;
    }
}

// ---------------- launcher -------------------------------------------------
extern "C" void kernel_launch(void* const* d_in, const int* in_sizes, int n_in,
                              void* d_out, int out_size) {
    const float* feature = (const float*)d_in[0];
    const float* spemb   = (const float*)d_in[1];
    const int*   src     = (const int*)d_in[2];
    const int*   dst     = (const int*)d_in[3];
    const int*   gids    = (const int*)d_in[4];
    const float* W[3]  = { (const float*)d_in[5], (const float*)d_in[6], (const float*)d_in[7] };
    const float* gm[3] = { (const float*)d_in[8], (const float*)d_in[10], (const float*)d_in[12] };
    const float* bt[3] = { (const float*)d_in[9], (const float*)d_in[11], (const float*)d_in[13] };
    const float* cW1  = (const float*)d_in[14];
    const float* cb1  = (const float*)d_in[15];
    const float* cg1  = (const float*)d_in[16];
    const float* cbt1 = (const float*)d_in[17];
    const float* cW2  = (const float*)d_in[18];
    const float* cb2  = (const float*)d_in[19];
    float* out = (float*)d_out;

    // CSR by dst + normalized edge directions (shared by all 3 layers)
    k_zero_cc<<<(N_NODES + 255) / 256, 256>>>();
    k_hist<<<(N_EDGES + 255) / 256, 256>>>(dst);
    k_scan<<<1, 1024>>>();
    k_scatter<<<(N_EDGES + 255) / 256, 256>>>(src, dst, spemb);

    int hin = 0, hout = 1;
    for (int L = 0; L < 3; L++) {
        k_edge_agg<<<(N_NODES * 32 + 255) / 256, 256>>>(feature, hin);
        k_gemm_relu<<<(N_NODES + BM - 1) / BM, 256>>>(W[L]);
        k_bn_stats<<<128, 256>>>();
        k_norm_pool<<<N_NODES / 8, 512>>>(feature, hin, hout, gm[L], bt[L], gids, L > 0 ? 1 : 0);
        k_classifier<<<1, 512>>>(cW1, cb1, cg1, cbt1, cW2, cb2, out, L > 0 ? 1 : 0);
        hin = hout;
        hout = (hout == 1) ? 2 : 1;
    }
}

// round 2
// speedup vs baseline: 1.1651x; 1.1651x over previous
#include <cuda_runtime.h>
#include <cuda_bf16.h>
#include <math.h>

#define N_NODES 25000
#define N_EDGES 400000
#define HID 64
#define EMB 8
#define N_GRAPHS 16
#define N_CLASSES 10
#define KDIM 512   /* EMB*HID */

// ---------------- scratch (device globals; no allocation allowed) ----------
__device__ float g_B[(size_t)N_NODES * KDIM];     // 51.2 MB  B[n, i*64+j]
__device__ float g_hA[N_NODES * HID];
__device__ float g_hB[N_NODES * HID];
__device__ float g_R[N_NODES * HID];              // relu(agg)
__device__ float g_D[(size_t)N_EDGES * EMB];      // directions in ORIGINAL edge order
__device__ int2  g_se[N_EDGES];                   // CSR-ordered {src, edge_id}
__device__ int   g_rowptr[N_NODES + 1];
__device__ int   g_cnt[N_NODES];
__device__ int   g_cur[N_NODES];
__device__ float g_sums[HID];
__device__ float g_sumsq[HID];
__device__ float g_pooled[N_GRAPHS * HID];

// ---------------- CSR build ------------------------------------------------
__global__ void k_zero_cc() {
    int i = blockIdx.x * blockDim.x + threadIdx.x;
    if (i < N_NODES) { g_cnt[i] = 0; g_cur[i] = 0; }
}

// histogram of dst + per-edge normalized direction (coalesced write, edge order)
__global__ void k_hist_dir(const int* __restrict__ src, const int* __restrict__ dst,
                           const float* __restrict__ c) {
    int e = blockIdx.x * blockDim.x + threadIdx.x;
    if (e >= N_EDGES) return;
    int s = src[e], t = dst[e];
    atomicAdd(&g_cnt[t], 1);
    float4 s0 = __ldg((const float4*)&c[s * EMB]);
    float4 s1 = __ldg((const float4*)&c[s * EMB + 4]);
    float4 t0 = __ldg((const float4*)&c[t * EMB]);
    float4 t1 = __ldg((const float4*)&c[t * EMB + 4]);
    float4 d0 = make_float4(s0.x - t0.x, s0.y - t0.y, s0.z - t0.z, s0.w - t0.w);
    float4 d1 = make_float4(s1.x - t1.x, s1.y - t1.y, s1.z - t1.z, s1.w - t1.w);
    float nn = d0.x * d0.x + d0.y * d0.y + d0.z * d0.z + d0.w * d0.w
             + d1.x * d1.x + d1.y * d1.y + d1.z * d1.z + d1.w * d1.w;
    float sc = 1.0f / fmaxf(sqrtf(nn), 1e-12f);
    d0.x *= sc; d0.y *= sc; d0.z *= sc; d0.w *= sc;
    d1.x *= sc; d1.y *= sc; d1.z *= sc; d1.w *= sc;
    *(float4*)&g_D[(size_t)e * EMB]     = d0;
    *(float4*)&g_D[(size_t)e * EMB + 4] = d1;
}

// single-block scan: 1024 threads x 25 contiguous counts each (25600 >= 25001)
__global__ void k_scan() {
    const int PER = 25;
    __shared__ int wsum[32];
    int tid = threadIdx.x, lane = tid & 31, wid = tid >> 5;
    int base = tid * PER;
    int v[PER];
    int s = 0;
    #pragma unroll
    for (int j = 0; j < PER; j++) {
        int i = base + j;
        int cv = (i < N_NODES) ? g_cnt[i] : 0;
        v[j] = s;          // exclusive local prefix
        s += cv;
    }
    int x = s;             // inclusive warp scan of per-thread totals
    #pragma unroll
    for (int o = 1; o < 32; o <<= 1) {
        int t = __shfl_up_sync(0xffffffffu, x, o);
        if (lane >= o) x += t;
    }
    if (lane == 31) wsum[wid] = x;
    __syncthreads();
    if (wid == 0) {
        int w = wsum[lane];
        #pragma unroll
        for (int o = 1; o < 32; o <<= 1) {
            int t = __shfl_up_sync(0xffffffffu, w, o);
            if (lane >= o) w += t;
        }
        wsum[lane] = w;
    }
    __syncthreads();
    int off = x - s + (wid > 0 ? wsum[wid - 1] : 0);   // exclusive prefix of this thread
    #pragma unroll
    for (int j = 0; j < PER; j++) {
        int i = base + j;
        if (i <= N_NODES) g_rowptr[i] = off + v[j];
    }
}

// scatter edge -> CSR slot; only 8 bytes scattered per edge
__global__ void k_scatter(const int* __restrict__ src, const int* __restrict__ dst) {
    int e = blockIdx.x * blockDim.x + threadIdx.x;
    if (e >= N_EDGES) return;
    int s = src[e], t = dst[e];
    int p = g_rowptr[t] + atomicAdd(&g_cur[t], 1);
    g_se[p] = make_int2(s, e);
}

// ---------------- edge aggregation: B[n,i,j] = sum_{e:dst=n} d_i * h[src,j] ----
// one warp per dst node, 16 accumulator regs = full 8x64 tile
__global__ void k_edge_agg(const float* __restrict__ feat, int hsel) {
    if (blockIdx.x == 0) {   // piggyback: zero per-layer reduction buffers
        int t = threadIdx.x;
        if (t < HID) { g_sums[t] = 0.f; g_sumsq[t] = 0.f; }
        for (int i = t; i < N_GRAPHS * HID; i += blockDim.x) g_pooled[i] = 0.f;
    }
    const float* __restrict__ h = (hsel == 0) ? feat : ((hsel == 1) ? g_hA : g_hB);
    int w = (blockIdx.x * blockDim.x + threadIdx.x) >> 5;
    int lane = threadIdx.x & 31;
    if (w >= N_NODES) return;
    int e0 = g_rowptr[w], e1 = g_rowptr[w + 1];
    float a0[EMB], a1[EMB];
    #pragma unroll
    for (int i = 0; i < EMB; i++) { a0[i] = 0.f; a1[i] = 0.f; }
    #pragma unroll 2
    for (int e = e0; e < e1; e++) {
        int2 se = __ldg(&g_se[e]);
        float4 d0 = __ldg((const float4*)&g_D[(size_t)se.y * EMB]);
        float4 d1 = __ldg((const float4*)&g_D[(size_t)se.y * EMB + 4]);
        float h0 = __ldg(&h[se.x * HID + lane]);
        float h1 = __ldg(&h[se.x * HID + 32 + lane]);
        a0[0] += d0.x * h0;  a1[0] += d0.x * h1;
        a0[1] += d0.y * h0;  a1[1] += d0.y * h1;
        a0[2] += d0.z * h0;  a1[2] += d0.z * h1;
        a0[3] += d0.w * h0;  a1[3] += d0.w * h1;
        a0[4] += d1.x * h0;  a1[4] += d1.x * h1;
        a0[5] += d1.y * h0;  a1[5] += d1.y * h1;
        a0[6] += d1.z * h0;  a1[6] += d1.z * h1;
        a0[7] += d1.w * h0;  a1[7] += d1.w * h1;
    }
    float* out = &g_B[(size_t)w * KDIM];
    #pragma unroll
    for (int i = 0; i < EMB; i++) {
        out[i * HID + lane] = a0[i];
        out[i * HID + 32 + lane] = a1[i];
    }
}

// ---------------- SGEMM: R = relu(B[25000,512] @ W[512,64]) + fused BN stats ---
#define BM 128
#define BK 32
__global__ void k_gemm_relu(const float* __restrict__ W) {
    __shared__ float As[BM][BK + 4];   // stride 36 floats
    __shared__ float Bs[BK][HID];
    int tid = threadIdx.x;       // 256
    int tx = tid & 15;           // col group: cols tx*4 .. tx*4+3
    int ty = tid >> 4;           // row group: rows ty*8 .. ty*8+7
    int rowBase = blockIdx.x * BM;
    float acc[8][4];
    #pragma unroll
    for (int r = 0; r < 8; r++)
        #pragma unroll
        for (int cc = 0; cc < 4; cc++) acc[r][cc] = 0.f;

    for (int kb = 0; kb < KDIM; kb += BK) {
        #pragma unroll
        for (int it = 0; it < 4; it++) {
            int f = tid + 256 * it;
            int r = f >> 3;
            int q = f & 7;
            int grow = rowBase + r;
            float4 v = make_float4(0.f, 0.f, 0.f, 0.f);
            if (grow < N_NODES)
                v = *(const float4*)&g_B[(size_t)grow * KDIM + kb + q * 4];
            *(float4*)&As[r][q * 4] = v;
        }
        #pragma unroll
        for (int it = 0; it < 2; it++) {
            int f = tid + 256 * it;
            int k = f >> 4;
            int q = f & 15;
            *(float4*)&Bs[k][q * 4] = *(const float4*)&W[(kb + k) * HID + q * 4];
        }
        __syncthreads();
        #pragma unroll
        for (int kk = 0; kk < BK; kk++) {
            float4 b4 = *(float4*)&Bs[kk][tx * 4];
            float a[8];
            #pragma unroll
            for (int r = 0; r < 8; r++) a[r] = As[ty * 8 + r][kk];
            #pragma unroll
            for (int r = 0; r < 8; r++) {
                acc[r][0] += a[r] * b4.x;
                acc[r][1] += a[r] * b4.y;
                acc[r][2] += a[r] * b4.z;
                acc[r][3] += a[r] * b4.w;
            }
        }
        __syncthreads();
    }
    // relu + store + fused column stats
    #pragma unroll
    for (int r = 0; r < 8; r++) {
        #pragma unroll
        for (int cc = 0; cc < 4; cc++) acc[r][cc] = fmaxf(acc[r][cc], 0.f);
        int grow = rowBase + ty * 8 + r;
        if (grow < N_NODES)
            *(float4*)&g_R[grow * HID + tx * 4] =
                make_float4(acc[r][0], acc[r][1], acc[r][2], acc[r][3]);
    }
    float* smr = &As[0][0];       // reuse: need 2048 floats, As has 4608
    #pragma unroll
    for (int cc = 0; cc < 4; cc++) {
        float s = 0.f, s2 = 0.f;
        #pragma unroll
        for (int r = 0; r < 8; r++) { s += acc[r][cc]; s2 += acc[r][cc] * acc[r][cc]; }
        smr[ty * HID + tx * 4 + cc] = s;
        smr[1024 + ty * HID + tx * 4 + cc] = s2;
    }
    __syncthreads();
    if (tid < HID) {
        float s = 0.f, s2 = 0.f;
        #pragma unroll
        for (int g = 0; g < 16; g++) {
            s  += smr[g * HID + tid];
            s2 += smr[1024 + g * HID + tid];
        }
        atomicAdd(&g_sums[tid], s);
        atomicAdd(&g_sumsq[tid], s2);
    }
}

// ---------------- BN normalize + shortcut + per-graph pooling --------------
__global__ void k_norm_pool(const float* __restrict__ feat, int hinsel, int houtsel,
                            const float* __restrict__ gamma, const float* __restrict__ beta,
                            const int* __restrict__ gids, int shortcut) {
    const float* __restrict__ hin = (hinsel == 0) ? feat : ((hinsel == 1) ? g_hA : g_hB);
    float* hout = (houtsel == 1) ? g_hA : g_hB;
    int tid = threadIdx.x;        // 512 -> 8 nodes x 64 cols per block
    int k = tid & 63, nl = tid >> 6;
    int n = blockIdx.x * 8 + nl;  // 3125*8 == 25000 exactly

    __shared__ float ps[N_GRAPHS * HID];
    for (int i = tid; i < N_GRAPHS * HID; i += 512) ps[i] = 0.f;
    __syncthreads();

    const float inv = 1.0f / (float)N_NODES;
    float mu = g_sums[k] * inv;
    float var = g_sumsq[k] * inv - mu * mu;
    float rstd = rsqrtf(var + 1e-5f);
    float v = gamma[k] * (g_R[n * HID + k] - mu) * rstd + beta[k];
    if (shortcut) v += hin[n * HID + k];
    hout[n * HID + k] = v;

    int g = gids[n];
    atomicAdd(&ps[g * HID + k], v);
    __syncthreads();

    int gmin = gids[blockIdx.x * 8];
    int gmax = gids[blockIdx.x * 8 + 7];        // ids sorted -> contiguous span
    int span = (gmax - gmin + 1) * HID;
    for (int i = tid; i < span; i += 512)
        atomicAdd(&g_pooled[gmin * HID + i], ps[gmin * HID + i]);
}

// ---------------- classifier on pooled [16,64] -----------------------------
__global__ void k_classifier(const float* __restrict__ cW1, const float* __restrict__ cb1,
                             const float* __restrict__ cg1, const float* __restrict__ cbt1,
                             const float* __restrict__ cW2, const float* __restrict__ cb2,
                             float* __restrict__ out, int accumulate) {
    __shared__ float xp[N_GRAPHS * HID];   // 1024
    __shared__ float y[N_GRAPHS * 32];     // 512
    __shared__ float mu[32], rs[32];
    int tid = threadIdx.x;  // 512
    for (int i = tid; i < N_GRAPHS * HID; i += 512) xp[i] = g_pooled[i];
    __syncthreads();
    {
        int r = tid >> 5, c = tid & 31;
        float acc = cb1[c];
        #pragma unroll 8
        for (int j = 0; j < HID; j++) acc += xp[r * HID + j] * cW1[j * 32 + c];
        y[r * 32 + c] = acc;
    }
    __syncthreads();
    if (tid < 32) {
        float s = 0.f, s2 = 0.f;
        #pragma unroll
        for (int r = 0; r < N_GRAPHS; r++) {
            float v = y[r * 32 + tid];
            s += v; s2 += v * v;
        }
        float m = s / (float)N_GRAPHS;
        float var = s2 / (float)N_GRAPHS - m * m;
        mu[tid] = m;
        rs[tid] = rsqrtf(var + 1e-5f);
    }
    __syncthreads();
    {
        int r = tid >> 5, c = tid & 31;
        float v = cg1[c] * (y[r * 32 + c] - mu[c]) * rs[c] + cbt1[c];
        y[r * 32 + c] = fmaxf(v, 0.f);
    }
    __syncthreads();
    if (tid < N_GRAPHS * N_CLASSES) {
        int r = tid / N_CLASSES, c = tid % N_CLASSES;
        float acc = cb2[c];
        #pragma unroll
        for (int j = 0; j < 32; j++) acc += y[r * 32 + j] * cW2[j * N_CLASSES + c];
        if (accumulate) out[r * N_CLASSES + c] += acc;
        else            out[r * N_CLASSES + c] = acc;
    }
}

// ---------------- launcher -------------------------------------------------
extern "C" void kernel_launch(void* const* d_in, const int* in_sizes, int n_in,
                              void* d_out, int out_size) {
    const float* feature = (const float*)d_in[0];
    const float* spemb   = (const float*)d_in[1];
    const int*   src     = (const int*)d_in[2];
    const int*   dst     = (const int*)d_in[3];
    const int*   gids    = (const int*)d_in[4];
    const float* W[3]  = { (const float*)d_in[5], (const float*)d_in[6], (const float*)d_in[7] };
    const float* gm[3] = { (const float*)d_in[8], (const float*)d_in[10], (const float*)d_in[12] };
    const float* bt[3] = { (const float*)d_in[9], (const float*)d_in[11], (const float*)d_in[13] };
    const float* cW1  = (const float*)d_in[14];
    const float* cb1  = (const float*)d_in[15];
    const float* cg1  = (const float*)d_in[16];
    const float* cbt1 = (const float*)d_in[17];
    const float* cW2  = (const float*)d_in[18];
    const float* cb2  = (const float*)d_in[19];
    float* out = (float*)d_out;

    // CSR by dst + normalized edge directions (shared by all 3 layers)
    k_zero_cc<<<(N_NODES + 255) / 256, 256>>>();
    k_hist_dir<<<(N_EDGES + 255) / 256, 256>>>(src, dst, spemb);
    k_scan<<<1, 1024>>>();
    k_scatter<<<(N_EDGES + 255) / 256, 256>>>(src, dst);

    int hin = 0, hout = 1;
    for (int L = 0; L < 3; L++) {
        k_edge_agg<<<(N_NODES * 32 + 255) / 256, 256>>>(feature, hin);
        k_gemm_relu<<<(N_NODES + BM - 1) / BM, 256>>>(W[L]);
        k_norm_pool<<<N_NODES / 8, 512>>>(feature, hin, hout, gm[L], bt[L], gids, L > 0 ? 1 : 0);
        k_classifier<<<1, 512>>>(cW1, cb1, cg1, cbt1, cW2, cb2, out, L > 0 ? 1 : 0);
        hin = hout;
        hout = (hout == 1) ? 2 : 1;
    }
}